// round 14
// baseline (speedup 1.0000x reference)
#include <cuda_runtime.h>
#include <cstdint>

// Problem dims (fixed by dataset)
#define BB 8
#define CC 96
#define GG 64   // PY*PX = 8*8
#define JJ 17
#define KK 96
#define NTHR 256
#define NWARPS (NTHR/32)
#define GSTRIDE 64
#define CELLS 2                         // c-cells per CTA
#define CELL_XY (JJ * GSTRIDE)
#define CELL_VAL (KK * JJ)
#define WIDTH_F 128.0f
#define LOG2E 1.4426950408889634f
#define INVIS_SENTINEL -1e19f

// Output layout: concat(oks_parts_sel [B,C,G,J], oks_person_sel [B,C,G], pose_gt [B,C,J,3])
#define PARTS_SZ  (BB*CC*GG*JJ)
#define PERSON_SZ (BB*CC*GG)
#define PERSON_OFF PARTS_SZ
#define POSE_OFF  (PARTS_SZ + PERSON_SZ)

typedef unsigned long long u64;

__device__ __forceinline__ float fast_ex2(float x) {
    float y;
    asm("ex2.approx.ftz.f32 %0, %1;" : "=f"(y) : "f"(x));
    return y;
}
__device__ __forceinline__ u64 pack_f32x2(float lo, float hi) {
    u64 r; asm("mov.b64 %0, {%1, %2};" : "=l"(r) : "f"(lo), "f"(hi)); return r;
}
__device__ __forceinline__ u64 add_f32x2(u64 a, u64 b) {
    u64 r; asm("add.rn.f32x2 %0, %1, %2;" : "=l"(r) : "l"(a), "l"(b)); return r;
}
__device__ __forceinline__ u64 mul_f32x2(u64 a, u64 b) {
    u64 r; asm("mul.rn.f32x2 %0, %1, %2;" : "=l"(r) : "l"(a), "l"(b)); return r;
}
__device__ __forceinline__ u64 fma_f32x2(u64 a, u64 b, u64 c) {
    u64 r; asm("fma.rn.f32x2 %0, %1, %2, %3;" : "=l"(r) : "l"(a), "l"(b), "l"(c)); return r;
}
__device__ __forceinline__ float2 unpack_f32x2(u64 v) {
    float2 f; asm("mov.b64 {%0, %1}, %2;" : "=f"(f.x), "=f"(f.y) : "l"(v)); return f;
}

__global__ __launch_bounds__(NTHR, 4)   // ~44KB smem/CTA -> 4+ CTAs/SM; 384 blocks single wave
void oks_assign_kernel(
    const float* __restrict__ pose_pool,   // [B,C,8,8,J,2]
    const float* __restrict__ keypoints,   // [B,K,J,3]
    const float* __restrict__ areas,       // [B,K]
    const float* __restrict__ transforms,  // [B,3,3]
    const float* __restrict__ tinv,        // [B,3,3]
    const int*   __restrict__ hflip,       // [B]
    const float* __restrict__ sigmas,      // [J]
    float* __restrict__ out)
{
    const int c0  = blockIdx.x * CELLS;    // first of two adjacent cells
    const int b   = blockIdx.y;
    const int tid  = threadIdx.x;
    const int wid  = tid >> 5;
    const int lane = tid & 31;

    __shared__ __align__(16) float s_x[CELLS * CELL_XY];
    __shared__ __align__(16) float s_y[CELLS * CELL_XY];
    __shared__ __align__(16) float s_nkx[KK * JJ];    // per-b tables, shared by both cells
    __shared__ __align__(16) float s_nky[KK * JJ];
    __shared__ __align__(16) float s_val[CELLS * CELL_VAL];
    __shared__ float s_score[CELLS * KK];
    __shared__ float s_ivs[KK];
    __shared__ float s_area[KK];
    __shared__ float s_sig[JJ];
    __shared__ float s_scjks[CELLS * JJ];
    __shared__ int   s_kstar[CELLS];

    const float ti00 = tinv[b*9+0], ti01 = tinv[b*9+1], ti02 = tinv[b*9+2];
    const float ti10 = tinv[b*9+3], ti11 = tinv[b*9+4], ti12 = tinv[b*9+5];
    const bool flip = hflip[b] > 0;

    if (tid < JJ) s_sig[tid] = sigmas[tid];
    if (tid < KK) s_area[tid] = areas[b*KK + tid];

    // ---- Phase A1: both cells' pools -> image coords (cells contiguous in memory) ----
    const float2* pp = (const float2*)(pose_pool + (size_t)(b*CC + c0) * GG * JJ * 2);
    for (int idx = tid; idx < CELLS*GG*JJ; idx += NTHR) {
        int cell = idx / (GG*JJ);
        int rem  = idx - cell*(GG*JJ);
        int g = rem / JJ, j = rem - g*JJ;
        float2 p = pp[idx];
        float fx = flip ? (WIDTH_F - 1.0f - p.x) : p.x;
        s_x[cell*CELL_XY + j*GSTRIDE + g] = fx*ti00 + p.y*ti01 + ti02;
        s_y[cell*CELL_XY + j*GSTRIDE + g] = fx*ti10 + p.y*ti11 + ti12;
    }

    // ---- Phase A2: negated keypoint tables, [k][j] layout (once per block) ----
    const float* kpt = keypoints + (size_t)b * KK * JJ * 3;
    for (int idx = tid; idx < KK*JJ; idx += NTHR) {
        float kx = kpt[idx*3 + 0];
        float ky = kpt[idx*3 + 1];
        float v  = kpt[idx*3 + 2];
        bool vis = v > 0.0f;
        s_nkx[idx] = vis ? -kx : INVIS_SENTINEL;   // invisible -> d2 ~1e38 -> ex2 -> +0
        s_nky[idx] = vis ? -ky : 0.0f;
    }

    // ---- Phase A3: vis_sum per k ----
    for (int k = tid; k < KK; k += NTHR) {
        float vs = 0.f;
        #pragma unroll
        for (int j = 0; j < JJ; j++)
            vs += (kpt[(k*JJ + j)*3 + 2] > 0.f) ? 1.0f : 0.0f;
        s_ivs[k] = 1.0f / fmaxf(vs, 1.0f);
    }
    __syncthreads();

    // ---- Phase B: 34 units (cell,j); coord loads hoisted, kk INNER (3-tile reuse) ----
    for (int u = wid; u < CELLS*JJ; u += NWARPS) {
        const int cell = (u >= JJ) ? 1 : 0;
        const int j    = u - cell*JJ;
        const float* rowx = s_x + cell*CELL_XY + j*GSTRIDE;
        const float* rowy = s_y + cell*CELL_XY + j*GSTRIDE;

        u64 nkx[3], nky[3];
        float mdA[3], mdB[3];
        #pragma unroll
        for (int kk = 0; kk < 3; kk++) {
            const int k = kk*32 + lane;
            float nx = s_nkx[k*JJ + j];   // lane stride 17 -> conflict-free
            float ny = s_nky[k*JJ + j];
            nkx[kk] = pack_f32x2(nx, nx);
            nky[kk] = pack_f32x2(ny, ny);
            mdA[kk] = 3.4e38f; mdB[kk] = 3.4e38f;
        }

        #pragma unroll 2
        for (int i = 0; i < GG/4; i++) {
            const ulonglong2 xx = *(const ulonglong2*)(rowx + i*4);  // broadcast 16B
            const ulonglong2 yy = *(const ulonglong2*)(rowy + i*4);
            #pragma unroll
            for (int kk = 0; kk < 3; kk++) {
                u64 dxa = add_f32x2(xx.x, nkx[kk]);
                u64 dxb = add_f32x2(xx.y, nkx[kk]);
                u64 dya = add_f32x2(yy.x, nky[kk]);
                u64 dyb = add_f32x2(yy.y, nky[kk]);
                u64 pa = fma_f32x2(dxa, dxa, mul_f32x2(dya, dya));
                u64 pb = fma_f32x2(dxb, dxb, mul_f32x2(dyb, dyb));
                float2 fa = unpack_f32x2(pa);
                float2 fb = unpack_f32x2(pb);
                mdA[kk] = fminf(mdA[kk], fminf(fa.x, fa.y));
                mdB[kk] = fminf(mdB[kk], fminf(fb.x, fb.y));
            }
        }

        const float sg = s_sig[j];
        const float c2 = 2.0f * (2.0f*sg) * (2.0f*sg);
        #pragma unroll
        for (int kk = 0; kk < 3; kk++) {
            const int k = kk*32 + lane;
            float denom = fmaxf(c2 * s_area[k], 1e-6f);
            float sc = __fdividef(-LOG2E, denom);
            s_val[cell*CELL_VAL + k*JJ + j] = fast_ex2(fminf(mdA[kk], mdB[kk]) * sc);
        }
    }
    __syncthreads();

    // ---- Phase B2: per-(cell,k) score (deterministic j order) ----
    for (int t = tid; t < CELLS*KK; t += NTHR) {
        int cell = t / KK, k = t - cell*KK;
        const float* v = s_val + cell*CELL_VAL + k*JJ;
        float s = 0.f;
        #pragma unroll
        for (int j = 0; j < JJ; j++) s += v[j];
        s_score[t] = s * s_ivs[k];
    }
    __syncthreads();

    // ---- Phase C: warps 0,1 do per-cell argmax (first-max) + scjks (same warp) ----
    if (wid < CELLS) {
        const int cell = wid;
        const float* sc = s_score + cell*KK;
        float bs = -1.0f; int bi = 0;
        #pragma unroll
        for (int p = 0; p < KK/32; p++) {
            int k = lane + p*32;
            float v = sc[k];
            if (v > bs) { bs = v; bi = k; }
        }
        #pragma unroll
        for (int off = 16; off > 0; off >>= 1) {
            float os = __shfl_xor_sync(0xffffffffu, bs, off);
            int   oi = __shfl_xor_sync(0xffffffffu, bi, off);
            if (os > bs || (os == bs && oi < bi)) { bs = os; bi = oi; }
        }
        if (lane == 0) s_kstar[cell] = bi;
        // bi is uniform across the warp after the full butterfly
        if (lane < JJ) {
            float sg = s_sig[lane];
            float denom = fmaxf(2.0f * (2.0f*sg) * (2.0f*sg) * s_area[bi], 1e-6f);
            s_scjks[cell*JJ + lane] = __fdividef(-LOG2E, denom);
        }
    }
    __syncthreads();

    // ---- Phase D: OKS maps for each cell's k* (branchless) ----
    for (int item = tid; item < CELLS*GG*JJ; item += NTHR) {
        int cell = item / (GG*JJ);
        int rem  = item - cell*(GG*JJ);
        int j = rem / GG, g = rem & (GG-1);
        int ks = s_kstar[cell];
        float dx = s_x[cell*CELL_XY + j*GSTRIDE + g] + s_nkx[ks*JJ + j];
        float dy = s_y[cell*CELL_XY + j*GSTRIDE + g] + s_nky[ks*JJ + j];
        s_val[cell*CELL_VAL + g*JJ + j] = fast_ex2(fmaf(dx, dx, dy*dy) * s_scjks[cell*JJ + j]);
    }
    __syncthreads();

    // ---- Phase E: emit outputs ----
    {   // parts: PER-CELL copy (cell stride in s_val is CELL_VAL=1632, map is 1088)
        #pragma unroll
        for (int cell = 0; cell < CELLS; cell++) {
            float4* parts4 = (float4*)(out + (size_t)(b*CC + c0 + cell) * GG * JJ);
            const float4* sv4 = (const float4*)(s_val + cell*CELL_VAL);
            for (int idx = tid; idx < (GG*JJ)/4; idx += NTHR) parts4[idx] = sv4[idx];
        }
    }

    {   // person: 2 cells x 64 g
        for (int t = tid; t < CELLS*GG; t += NTHR) {
            int cell = t / GG, g = t - cell*GG;
            const float* v = s_val + cell*CELL_VAL + g*JJ;
            float s = 0.f;
            #pragma unroll
            for (int j = 0; j < JJ; j++) s += v[j];
            out[PERSON_OFF + (size_t)(b*CC + c0 + cell) * GG + g] = s * s_ivs[s_kstar[cell]];
        }
    }

    if (tid < CELLS*JJ) {
        int cell = tid / JJ, j = tid - cell*JJ;
        int ks = s_kstar[cell];
        float X = kpt[(ks*JJ + j)*3 + 0];
        float Y = kpt[(ks*JJ + j)*3 + 1];
        float V = kpt[(ks*JJ + j)*3 + 2];
        float t00 = transforms[b*9+0], t01 = transforms[b*9+1], t02 = transforms[b*9+2];
        float t10 = transforms[b*9+3], t11 = transforms[b*9+4], t12 = transforms[b*9+5];
        float gx = t00*X + t01*Y + t02;
        float gy = t10*X + t11*Y + t12;
        if (flip) gx = WIDTH_F - 1.0f - gx;
        float sg = 2.0f * s_sig[j];
        float gv = (V > 0.f) ? (t00 * t11) * (s_area[ks] * sg * sg) : 0.0f;
        float* pg = out + POSE_OFF + (size_t)((b*CC + c0 + cell)*JJ + j) * 3;
        pg[0] = gx; pg[1] = gy; pg[2] = gv;
    }
}

extern "C" void kernel_launch(void* const* d_in, const int* in_sizes, int n_in,
                              void* d_out, int out_size) {
    const float* pose_pool  = (const float*)d_in[0];
    const float* keypoints  = (const float*)d_in[1];
    const float* areas      = (const float*)d_in[2];
    const float* transforms = (const float*)d_in[3];
    const float* tinv       = (const float*)d_in[4];
    const int*   hflip      = (const int*)  d_in[5];
    const float* sigmas     = (const float*)d_in[6];
    float* out = (float*)d_out;

    dim3 grid(CC/CELLS, BB);
    oks_assign_kernel<<<grid, NTHR>>>(pose_pool, keypoints, areas, transforms,
                                      tinv, hflip, sigmas, out);
}

// round 15
// speedup vs baseline: 1.0189x; 1.0189x over previous
#include <cuda_runtime.h>
#include <cstdint>

// Problem dims (fixed by dataset)
#define BB 8
#define CC 96
#define GG 64   // PY*PX = 8*8
#define JJ 17
#define KK 96
#define NTHR 256
#define NWARPS (NTHR/32)
#define GSTRIDE 64
#define WIDTH_F 128.0f
#define LOG2E 1.4426950408889634f
#define INVIS_SENTINEL -1e19f

// Output layout: concat(oks_parts_sel [B,C,G,J], oks_person_sel [B,C,G], pose_gt [B,C,J,3])
#define PARTS_SZ  (BB*CC*GG*JJ)
#define PERSON_SZ (BB*CC*GG)
#define PERSON_OFF PARTS_SZ
#define POSE_OFF  (PARTS_SZ + PERSON_SZ)

typedef unsigned long long u64;

__device__ __forceinline__ float fast_ex2(float x) {
    float y;
    asm("ex2.approx.ftz.f32 %0, %1;" : "=f"(y) : "f"(x));
    return y;
}
__device__ __forceinline__ u64 pack_f32x2(float lo, float hi) {
    u64 r; asm("mov.b64 %0, {%1, %2};" : "=l"(r) : "f"(lo), "f"(hi)); return r;
}
__device__ __forceinline__ u64 add_f32x2(u64 a, u64 b) {
    u64 r; asm("add.rn.f32x2 %0, %1, %2;" : "=l"(r) : "l"(a), "l"(b)); return r;
}
__device__ __forceinline__ u64 mul_f32x2(u64 a, u64 b) {
    u64 r; asm("mul.rn.f32x2 %0, %1, %2;" : "=l"(r) : "l"(a), "l"(b)); return r;
}
__device__ __forceinline__ u64 fma_f32x2(u64 a, u64 b, u64 c) {
    u64 r; asm("fma.rn.f32x2 %0, %1, %2, %3;" : "=l"(r) : "l"(a), "l"(b), "l"(c)); return r;
}
__device__ __forceinline__ float2 unpack_f32x2(u64 v) {
    float2 f; asm("mov.b64 {%0, %1}, %2;" : "=f"(f.x), "=f"(f.y) : "l"(v)); return f;
}

__global__ __launch_bounds__(NTHR, 6)   // ~36KB smem -> 6 CTAs/SM; 888 slots >= 768: single wave
void oks_assign_kernel(
    const float* __restrict__ pose_pool,   // [B,C,8,8,J,2]
    const float* __restrict__ keypoints,   // [B,K,J,3]
    const float* __restrict__ areas,       // [B,K]
    const float* __restrict__ transforms,  // [B,3,3]
    const float* __restrict__ tinv,        // [B,3,3]
    const int*   __restrict__ hflip,       // [B]
    const float* __restrict__ sigmas,      // [J]
    float* __restrict__ out)
{
    const int c = blockIdx.x;
    const int b = blockIdx.y;
    const int tid  = threadIdx.x;
    const int wid  = tid >> 5;
    const int lane = tid & 31;

    __shared__ __align__(16) float s_x[JJ * GSTRIDE];
    __shared__ __align__(16) float s_y[JJ * GSTRIDE];
    __shared__ __align__(16) float s_nkx[KK * JJ];    // [k][j] stride 17: conflict-free
    __shared__ __align__(16) float s_nky[KK * JJ];
    __shared__ __align__(16) float s_p0[KK * JJ];     // min d^2 over g in [0,32)
    __shared__ __align__(16) float s_p1[KK * JJ];     // min d^2 over g in [32,64)
    __shared__ float s_score[KK];
    __shared__ float s_ivs[KK];
    __shared__ float s_area[KK];
    __shared__ float s_sig[JJ];
    __shared__ float s_scjks[JJ];
    __shared__ int   s_kstar;

    const float ti00 = tinv[b*9+0], ti01 = tinv[b*9+1], ti02 = tinv[b*9+2];
    const float ti10 = tinv[b*9+3], ti11 = tinv[b*9+4], ti12 = tinv[b*9+5];
    const bool flip = hflip[b] > 0;

    if (tid < JJ) s_sig[tid] = sigmas[tid];
    if (tid < KK) s_area[tid] = areas[b*KK + tid];

    // ---- Phase A1: pool -> image coords; batched loads (MLP 4-5) ----
    const float2* pp = (const float2*)(pose_pool + (size_t)(b*CC + c) * GG * JJ * 2);
    {
        float2 pv[4];
        #pragma unroll
        for (int t = 0; t < 4; t++) pv[t] = pp[tid + t*NTHR];        // 1024 <= 1088: all valid
        const bool has5 = tid < (GG*JJ - 4*NTHR);                     // 64 threads
        float2 pv4 = has5 ? pp[tid + 4*NTHR] : make_float2(0.f, 0.f);

        #pragma unroll
        for (int t = 0; t < 4; t++) {
            int idx = tid + t*NTHR;
            int g = idx / JJ, j = idx - g*JJ;
            float fx = flip ? (WIDTH_F - 1.0f - pv[t].x) : pv[t].x;
            s_x[j*GSTRIDE + g] = fx*ti00 + pv[t].y*ti01 + ti02;
            s_y[j*GSTRIDE + g] = fx*ti10 + pv[t].y*ti11 + ti12;
        }
        if (has5) {
            int idx = tid + 4*NTHR;
            int g = idx / JJ, j = idx - g*JJ;
            float fx = flip ? (WIDTH_F - 1.0f - pv4.x) : pv4.x;
            s_x[j*GSTRIDE + g] = fx*ti00 + pv4.y*ti01 + ti02;
            s_y[j*GSTRIDE + g] = fx*ti10 + pv4.y*ti11 + ti12;
        }
    }

    // ---- Phase A2: negated keypoint tables, [k][j] layout ----
    const float* kpt = keypoints + (size_t)b * KK * JJ * 3;
    for (int idx = tid; idx < KK*JJ; idx += NTHR) {
        float kx = kpt[idx*3 + 0];
        float ky = kpt[idx*3 + 1];
        float v  = kpt[idx*3 + 2];
        bool vis = v > 0.0f;
        s_nkx[idx] = vis ? -kx : INVIS_SENTINEL;   // invisible -> d2 ~1e38 -> ex2 -> +0
        s_nky[idx] = vis ? -ky : 0.0f;
    }

    // ---- Phase A3: vis_sum per k (gmem, L1-hot) ----
    for (int k = tid; k < KK; k += NTHR) {
        float vs = 0.f;
        #pragma unroll
        for (int j = 0; j < JJ; j++)
            vs += (kpt[(k*JJ + j)*3 + 2] > 0.f) ? 1.0f : 0.0f;
        s_ivs[k] = 1.0f / fmaxf(vs, 1.0f);
    }
    __syncthreads();

    // ---- Phase B: 34 balanced units = (j, g-half of 32); kk INNER (3-tile load reuse) ----
    // Writes min-d^2 partials; min is exact so association is irrelevant.
    for (int u = wid; u < 2*JJ; u += NWARPS) {
        const int j   = u >> 1;
        const int off = (u & 1) << 5;     // 0 or 32
        const float* rowx = s_x + j*GSTRIDE + off;
        const float* rowy = s_y + j*GSTRIDE + off;
        float* dst = (u & 1) ? s_p1 : s_p0;

        u64 nkx[3], nky[3];
        float mdA[3], mdB[3];
        #pragma unroll
        for (int kk = 0; kk < 3; kk++) {
            const int k = kk*32 + lane;
            float nx = s_nkx[k*JJ + j];   // lane stride 17 -> conflict-free
            float ny = s_nky[k*JJ + j];
            nkx[kk] = pack_f32x2(nx, nx);
            nky[kk] = pack_f32x2(ny, ny);
            mdA[kk] = 3.4e38f; mdB[kk] = 3.4e38f;
        }

        #pragma unroll 2
        for (int i = 0; i < 8; i++) {     // 32 points
            const ulonglong2 xx = *(const ulonglong2*)(rowx + i*4);  // broadcast 16B
            const ulonglong2 yy = *(const ulonglong2*)(rowy + i*4);
            #pragma unroll
            for (int kk = 0; kk < 3; kk++) {
                u64 dxa = add_f32x2(xx.x, nkx[kk]);
                u64 dxb = add_f32x2(xx.y, nkx[kk]);
                u64 dya = add_f32x2(yy.x, nky[kk]);
                u64 dyb = add_f32x2(yy.y, nky[kk]);
                u64 pa = fma_f32x2(dxa, dxa, mul_f32x2(dya, dya));
                u64 pb = fma_f32x2(dxb, dxb, mul_f32x2(dyb, dyb));
                float2 fa = unpack_f32x2(pa);
                float2 fb = unpack_f32x2(pb);
                mdA[kk] = fminf(mdA[kk], fminf(fa.x, fa.y));
                mdB[kk] = fminf(mdB[kk], fminf(fb.x, fb.y));
            }
        }

        #pragma unroll
        for (int kk = 0; kk < 3; kk++) {
            const int k = kk*32 + lane;
            dst[k*JJ + j] = fminf(mdA[kk], mdB[kk]);
        }
    }
    __syncthreads();

    // ---- Phase B2: one thread per k: combine halves, ex2, sum over j (ascending) ----
    if (tid < KK) {
        const int k = tid;
        const float ia = s_area[k];
        float s = 0.f;
        #pragma unroll
        for (int j = 0; j < JJ; j++) {
            float m = fminf(s_p0[k*JJ + j], s_p1[k*JJ + j]);
            float sg = s_sig[j];
            float c2 = 2.0f * (2.0f*sg) * (2.0f*sg);
            float denom = fmaxf(c2 * ia, 1e-6f);
            float sc = __fdividef(-LOG2E, denom);
            s += fast_ex2(m * sc);
        }
        s_score[k] = s * s_ivs[k];
    }
    __syncthreads();

    // ---- Phase C: warp 0 argmax (first-max semantics) + scjks in same warp ----
    if (tid < 32) {
        float bs = -1.0f; int bi = 0;
        #pragma unroll
        for (int p = 0; p < KK/32; p++) {
            int k = tid + p*32;
            float sc = s_score[k];
            if (sc > bs) { bs = sc; bi = k; }
        }
        #pragma unroll
        for (int off = 16; off > 0; off >>= 1) {
            float os = __shfl_xor_sync(0xffffffffu, bs, off);
            int   oi = __shfl_xor_sync(0xffffffffu, bi, off);
            if (os > bs || (os == bs && oi < bi)) { bs = os; bi = oi; }
        }
        if (tid == 0) s_kstar = bi;
        // bi is uniform after the full butterfly
        if (tid < JJ) {
            float sg = s_sig[tid];
            float denom = fmaxf(2.0f * (2.0f*sg) * (2.0f*sg) * s_area[bi], 1e-6f);
            s_scjks[tid] = __fdividef(-LOG2E, denom);
        }
    }
    __syncthreads();
    const int ks = s_kstar;

    // ---- Phase D+E fused: thread g computes k*'s 17 oks, stores parts + person ----
    if (tid < GG) {
        const int g = tid;
        float* pdst = out + (size_t)(b*CC + c) * GG * JJ + g*JJ;
        float acc = 0.f;
        #pragma unroll
        for (int j = 0; j < JJ; j++) {
            float dx = s_x[j*GSTRIDE + g] + s_nkx[ks*JJ + j];
            float dy = s_y[j*GSTRIDE + g] + s_nky[ks*JJ + j];
            float o = fast_ex2(fmaf(dx, dx, dy*dy) * s_scjks[j]);
            pdst[j] = o;
            acc += o;
        }
        out[PERSON_OFF + (size_t)(b*CC + c) * GG + g] = acc * s_ivs[ks];
    }

    if (tid >= 64 && tid < 64 + JJ) {
        int j = tid - 64;
        float X = kpt[(ks*JJ + j)*3 + 0];
        float Y = kpt[(ks*JJ + j)*3 + 1];
        float V = kpt[(ks*JJ + j)*3 + 2];
        float t00 = transforms[b*9+0], t01 = transforms[b*9+1], t02 = transforms[b*9+2];
        float t10 = transforms[b*9+3], t11 = transforms[b*9+4], t12 = transforms[b*9+5];
        float gx = t00*X + t01*Y + t02;
        float gy = t10*X + t11*Y + t12;
        if (flip) gx = WIDTH_F - 1.0f - gx;
        float sg = 2.0f * s_sig[j];
        float gv = (V > 0.f) ? (t00 * t11) * (s_area[ks] * sg * sg) : 0.0f;
        float* pg = out + POSE_OFF + (size_t)((b*CC + c)*JJ + j) * 3;
        pg[0] = gx; pg[1] = gy; pg[2] = gv;
    }
}

extern "C" void kernel_launch(void* const* d_in, const int* in_sizes, int n_in,
                              void* d_out, int out_size) {
    const float* pose_pool  = (const float*)d_in[0];
    const float* keypoints  = (const float*)d_in[1];
    const float* areas      = (const float*)d_in[2];
    const float* transforms = (const float*)d_in[3];
    const float* tinv       = (const float*)d_in[4];
    const int*   hflip      = (const int*)  d_in[5];
    const float* sigmas     = (const float*)d_in[6];
    float* out = (float*)d_out;

    dim3 grid(CC, BB);
    oks_assign_kernel<<<grid, NTHR>>>(pose_pool, keypoints, areas, transforms,
                                      tinv, hflip, sigmas, out);
}

// round 16
// speedup vs baseline: 1.0909x; 1.0707x over previous
#include <cuda_runtime.h>
#include <cstdint>

// Problem dims (fixed by dataset)
#define BB 8
#define CC 96
#define GG 64   // PY*PX = 8*8
#define JJ 17
#define KK 96
#define NTHR 256
#define NWARPS (NTHR/32)
#define GSTRIDE 68            // 272B rows: 16B-aligned, A1 STS conflicts <=2-way
#define WIDTH_F 128.0f
#define LOG2E 1.4426950408889634f
#define INVIS_SENTINEL -1e19f

// Output layout: concat(oks_parts_sel [B,C,G,J], oks_person_sel [B,C,G], pose_gt [B,C,J,3])
#define PARTS_SZ  (BB*CC*GG*JJ)
#define PERSON_SZ (BB*CC*GG)
#define PERSON_OFF PARTS_SZ
#define POSE_OFF  (PARTS_SZ + PERSON_SZ)

typedef unsigned long long u64;

__device__ __forceinline__ float fast_ex2(float x) {
    float y;
    asm("ex2.approx.ftz.f32 %0, %1;" : "=f"(y) : "f"(x));
    return y;
}
__device__ __forceinline__ u64 pack_f32x2(float lo, float hi) {
    u64 r; asm("mov.b64 %0, {%1, %2};" : "=l"(r) : "f"(lo), "f"(hi)); return r;
}
__device__ __forceinline__ u64 add_f32x2(u64 a, u64 b) {
    u64 r; asm("add.rn.f32x2 %0, %1, %2;" : "=l"(r) : "l"(a), "l"(b)); return r;
}
__device__ __forceinline__ u64 mul_f32x2(u64 a, u64 b) {
    u64 r; asm("mul.rn.f32x2 %0, %1, %2;" : "=l"(r) : "l"(a), "l"(b)); return r;
}
__device__ __forceinline__ u64 fma_f32x2(u64 a, u64 b, u64 c) {
    u64 r; asm("fma.rn.f32x2 %0, %1, %2, %3;" : "=l"(r) : "l"(a), "l"(b), "l"(c)); return r;
}
__device__ __forceinline__ float2 unpack_f32x2(u64 v) {
    float2 f; asm("mov.b64 {%0, %1}, %2;" : "=f"(f.x), "=f"(f.y) : "l"(v)); return f;
}

// min over 4 points (two packed pairs of d^2)
__device__ __forceinline__ float min4_d2(const ulonglong2 xx, const ulonglong2 yy,
                                         u64 nkx, u64 nky) {
    u64 dxa = add_f32x2(xx.x, nkx);
    u64 dxb = add_f32x2(xx.y, nkx);
    u64 dya = add_f32x2(yy.x, nky);
    u64 dyb = add_f32x2(yy.y, nky);
    u64 pa = fma_f32x2(dxa, dxa, mul_f32x2(dya, dya));
    u64 pb = fma_f32x2(dxb, dxb, mul_f32x2(dyb, dyb));
    float2 fa = unpack_f32x2(pa);
    float2 fb = unpack_f32x2(pb);
    return fminf(fminf(fa.x, fa.y), fminf(fb.x, fb.y));
}

__global__ __launch_bounds__(NTHR, 5)   // 48-reg cap; 740 slots ~= 1.04 waves (R7-proven)
void oks_assign_kernel(
    const float* __restrict__ pose_pool,   // [B,C,8,8,J,2]
    const float* __restrict__ keypoints,   // [B,K,J,3]
    const float* __restrict__ areas,       // [B,K]
    const float* __restrict__ transforms,  // [B,3,3]
    const float* __restrict__ tinv,        // [B,3,3]
    const int*   __restrict__ hflip,       // [B]
    const float* __restrict__ sigmas,      // [J]
    float* __restrict__ out)
{
    const int c = blockIdx.x;
    const int b = blockIdx.y;
    const int tid  = threadIdx.x;
    const int wid  = tid >> 5;
    const int lane = tid & 31;

    __shared__ __align__(16) float s_x[JJ * GSTRIDE];
    __shared__ __align__(16) float s_y[JJ * GSTRIDE];
    __shared__ __align__(16) float s_nkx[KK * JJ];    // [k][j] stride 17: conflict-free
    __shared__ __align__(16) float s_nky[KK * JJ];
    __shared__ __align__(16) float s_p0[KK * JJ];     // min d^2 over g in [0,32)
    __shared__ __align__(16) float s_p1[KK * JJ];     // min d^2 over g in [32,64)
    __shared__ float s_score[KK];
    __shared__ float s_ivs[KK];
    __shared__ float s_area[KK];
    __shared__ float s_sig[JJ];
    __shared__ float s_scjks[JJ];
    __shared__ int   s_kstar;

    const float ti00 = tinv[b*9+0], ti01 = tinv[b*9+1], ti02 = tinv[b*9+2];
    const float ti10 = tinv[b*9+3], ti11 = tinv[b*9+4], ti12 = tinv[b*9+5];
    const bool flip = hflip[b] > 0;

    if (tid < JJ) s_sig[tid] = sigmas[tid];
    if (tid < KK) s_area[tid] = areas[b*KK + tid];

    // ---- Phase A1: pool -> image coords; batched loads (MLP 4-5); stride-68 rows ----
    const float2* pp = (const float2*)(pose_pool + (size_t)(b*CC + c) * GG * JJ * 2);
    {
        float2 pv[4];
        #pragma unroll
        for (int t = 0; t < 4; t++) pv[t] = pp[tid + t*NTHR];        // 1024 <= 1088: all valid
        const bool has5 = tid < (GG*JJ - 4*NTHR);                     // 64 threads
        float2 pv4 = has5 ? pp[tid + 4*NTHR] : make_float2(0.f, 0.f);

        #pragma unroll
        for (int t = 0; t < 4; t++) {
            int idx = tid + t*NTHR;
            int g = idx / JJ, j = idx - g*JJ;
            float fx = flip ? (WIDTH_F - 1.0f - pv[t].x) : pv[t].x;
            s_x[j*GSTRIDE + g] = fx*ti00 + pv[t].y*ti01 + ti02;
            s_y[j*GSTRIDE + g] = fx*ti10 + pv[t].y*ti11 + ti12;
        }
        if (has5) {
            int idx = tid + 4*NTHR;
            int g = idx / JJ, j = idx - g*JJ;
            float fx = flip ? (WIDTH_F - 1.0f - pv4.x) : pv4.x;
            s_x[j*GSTRIDE + g] = fx*ti00 + pv4.y*ti01 + ti02;
            s_y[j*GSTRIDE + g] = fx*ti10 + pv4.y*ti11 + ti12;
        }
    }

    // ---- Phase A2: negated keypoint tables, [k][j] layout ----
    const float* kpt = keypoints + (size_t)b * KK * JJ * 3;
    for (int idx = tid; idx < KK*JJ; idx += NTHR) {
        float kx = kpt[idx*3 + 0];
        float ky = kpt[idx*3 + 1];
        float v  = kpt[idx*3 + 2];
        bool vis = v > 0.0f;
        s_nkx[idx] = vis ? -kx : INVIS_SENTINEL;   // invisible -> d2 ~1e38 -> ex2 -> +0
        s_nky[idx] = vis ? -ky : 0.0f;
    }

    // ---- Phase A3: vis_sum per k (gmem, L1-hot) ----
    for (int k = tid; k < KK; k += NTHR) {
        float vs = 0.f;
        #pragma unroll
        for (int j = 0; j < JJ; j++)
            vs += (kpt[(k*JJ + j)*3 + 2] > 0.f) ? 1.0f : 0.0f;
        s_ivs[k] = 1.0f / fmaxf(vs, 1.0f);
    }
    __syncthreads();

    // ---- Phase B: unit = whole j; dual g-half streams, kk inner (one setup per j) ----
    for (int j = wid; j < JJ; j += NWARPS) {
        const float* rowx = s_x + j*GSTRIDE;
        const float* rowy = s_y + j*GSTRIDE;

        u64 nkx[3], nky[3];
        float md0[3], md1[3];
        #pragma unroll
        for (int kk = 0; kk < 3; kk++) {
            const int k = kk*32 + lane;
            float nx = s_nkx[k*JJ + j];   // lane stride 17 -> conflict-free
            float ny = s_nky[k*JJ + j];
            nkx[kk] = pack_f32x2(nx, nx);
            nky[kk] = pack_f32x2(ny, ny);
            md0[kk] = 3.4e38f; md1[kk] = 3.4e38f;
        }

        #pragma unroll 2
        for (int i = 0; i < 8; i++) {
            const ulonglong2 xx0 = *(const ulonglong2*)(rowx + i*4);        // broadcast 16B
            const ulonglong2 yy0 = *(const ulonglong2*)(rowy + i*4);
            const ulonglong2 xx1 = *(const ulonglong2*)(rowx + 32 + i*4);
            const ulonglong2 yy1 = *(const ulonglong2*)(rowy + 32 + i*4);
            #pragma unroll
            for (int kk = 0; kk < 3; kk++) {
                md0[kk] = fminf(md0[kk], min4_d2(xx0, yy0, nkx[kk], nky[kk]));
                md1[kk] = fminf(md1[kk], min4_d2(xx1, yy1, nkx[kk], nky[kk]));
            }
        }

        #pragma unroll
        for (int kk = 0; kk < 3; kk++) {
            const int k = kk*32 + lane;
            s_p0[k*JJ + j] = md0[kk];
            s_p1[k*JJ + j] = md1[kk];
        }
    }
    __syncthreads();

    // ---- Phase B2: one thread per k: combine halves, ex2, sum over j (ascending) ----
    if (tid < KK) {
        const int k = tid;
        const float ia = s_area[k];
        float s = 0.f;
        #pragma unroll
        for (int j = 0; j < JJ; j++) {
            float m = fminf(s_p0[k*JJ + j], s_p1[k*JJ + j]);
            float sg = s_sig[j];
            float c2 = 2.0f * (2.0f*sg) * (2.0f*sg);
            float denom = fmaxf(c2 * ia, 1e-6f);
            float sc = __fdividef(-LOG2E, denom);
            s += fast_ex2(m * sc);
        }
        s_score[k] = s * s_ivs[k];
    }
    __syncthreads();

    // ---- Phase C: warp 0 argmax (first-max semantics) + scjks in same warp ----
    if (tid < 32) {
        float bs = -1.0f; int bi = 0;
        #pragma unroll
        for (int p = 0; p < KK/32; p++) {
            int k = tid + p*32;
            float sc = s_score[k];
            if (sc > bs) { bs = sc; bi = k; }
        }
        #pragma unroll
        for (int off = 16; off > 0; off >>= 1) {
            float os = __shfl_xor_sync(0xffffffffu, bs, off);
            int   oi = __shfl_xor_sync(0xffffffffu, bi, off);
            if (os > bs || (os == bs && oi < bi)) { bs = os; bi = oi; }
        }
        if (tid == 0) s_kstar = bi;
        // bi is uniform after the full butterfly
        if (tid < JJ) {
            float sg = s_sig[tid];
            float denom = fmaxf(2.0f * (2.0f*sg) * (2.0f*sg) * s_area[bi], 1e-6f);
            s_scjks[tid] = __fdividef(-LOG2E, denom);
        }
    }
    __syncthreads();
    const int ks = s_kstar;

    // ---- Phase D+E fused: thread g computes k*'s 17 oks, stores parts + person ----
    if (tid < GG) {
        const int g = tid;
        float* pdst = out + (size_t)(b*CC + c) * GG * JJ + g*JJ;
        float acc = 0.f;
        #pragma unroll
        for (int j = 0; j < JJ; j++) {
            float dx = s_x[j*GSTRIDE + g] + s_nkx[ks*JJ + j];
            float dy = s_y[j*GSTRIDE + g] + s_nky[ks*JJ + j];
            float o = fast_ex2(fmaf(dx, dx, dy*dy) * s_scjks[j]);
            pdst[j] = o;
            acc += o;
        }
        out[PERSON_OFF + (size_t)(b*CC + c) * GG + g] = acc * s_ivs[ks];
    }

    if (tid >= 64 && tid < 64 + JJ) {
        int j = tid - 64;
        float X = kpt[(ks*JJ + j)*3 + 0];
        float Y = kpt[(ks*JJ + j)*3 + 1];
        float V = kpt[(ks*JJ + j)*3 + 2];
        float t00 = transforms[b*9+0], t01 = transforms[b*9+1], t02 = transforms[b*9+2];
        float t10 = transforms[b*9+3], t11 = transforms[b*9+4], t12 = transforms[b*9+5];
        float gx = t00*X + t01*Y + t02;
        float gy = t10*X + t11*Y + t12;
        if (flip) gx = WIDTH_F - 1.0f - gx;
        float sg = 2.0f * s_sig[j];
        float gv = (V > 0.f) ? (t00 * t11) * (s_area[ks] * sg * sg) : 0.0f;
        float* pg = out + POSE_OFF + (size_t)((b*CC + c)*JJ + j) * 3;
        pg[0] = gx; pg[1] = gy; pg[2] = gv;
    }
}

extern "C" void kernel_launch(void* const* d_in, const int* in_sizes, int n_in,
                              void* d_out, int out_size) {
    const float* pose_pool  = (const float*)d_in[0];
    const float* keypoints  = (const float*)d_in[1];
    const float* areas      = (const float*)d_in[2];
    const float* transforms = (const float*)d_in[3];
    const float* tinv       = (const float*)d_in[4];
    const int*   hflip      = (const int*)  d_in[5];
    const float* sigmas     = (const float*)d_in[6];
    float* out = (float*)d_out;

    dim3 grid(CC, BB);
    oks_assign_kernel<<<grid, NTHR>>>(pose_pool, keypoints, areas, transforms,
                                      tinv, hflip, sigmas, out);
}